// round 1
// baseline (speedup 1.0000x reference)
#include <cuda_runtime.h>

#define B_ 8
#define L_ 2048
#define D_ 1024
#define NTOT (B_ * L_)       /* 16384 rows */
#define K_ (2 * D_)          /* 2048 reduction dim */

#define BM 128
#define BN 128               /* 64 input-gate cols + 64 forget-gate cols */
#define BK 16
#define TM 8
#define TN 8

__device__ __forceinline__ float sigmoidf_(float x) {
    return 1.0f / (1.0f + __expf(-x));
}

// ---------------------------------------------------------------------------
// Kernel 1: cumulative average. One thread per (b, d) column; at each step t
// the warp's 32 threads read 32 consecutive floats (fully coalesced).
// avg[b,t,d] = (sum_{s<=t} x[b,s,d]) / (t+1)   -- matches jnp.cumsum/denom.
// ---------------------------------------------------------------------------
__global__ void cumavg_kernel(const float* __restrict__ x, float* __restrict__ avg) {
    int col = blockIdx.x * blockDim.x + threadIdx.x;   // 0 .. B*D-1
    int b = col >> 10;            // / D_
    int d = col & (D_ - 1);
    const float* xp = x + (size_t)b * L_ * D_ + d;
    float* ap = avg + (size_t)b * L_ * D_ + d;
    float sum = 0.0f;
#pragma unroll 8
    for (int t = 0; t < L_; ++t) {
        sum += __ldg(xp + (size_t)t * D_);
        ap[(size_t)t * D_] = sum / (float)(t + 1);
    }
}

// ---------------------------------------------------------------------------
// Kernel 2: fused GEMM + gating epilogue.
//   g[n, o] = sum_k cat[n, k] * W[o, k] + bias[o]
//   cat[n, k] = (k < D) ? X[n, k] : AVG[n, k - D]
// Each block computes a 128x128 tile of g where the 128 columns are
// {o .. o+63} (input gate) and {o+1024 .. o+1087} (forget gate) for the SAME
// 64 output dims d -> epilogue needs no cross-thread exchange:
// thread microtile cols j<4 hold gin(d), cols j>=4 hold gfg(d).
//   out[n, d] = sig(gin)*X[n,d] + sig(gfg)*AVG[n,d]
// ---------------------------------------------------------------------------
__global__ __launch_bounds__(256, 2)
void gate_gemm_kernel(const float* __restrict__ X,
                      const float* __restrict__ AV,
                      const float* __restrict__ W,
                      const float* __restrict__ bias,
                      float* __restrict__ out)
{
    __shared__ float As[BK][BM];   // 8 KB
    __shared__ float Bs[BK][BN];   // 8 KB

    const int tid = threadIdx.x;
    const int tx  = tid & 15;      // 16 thread-cols
    const int ty  = tid >> 4;      // 16 thread-rows
    const int bn  = blockIdx.x;    // 0..15  (64 output dims each)
    const int bm  = blockIdx.y;    // 0..127 (128 rows each)

    const int row0 = bm * BM;

    float acc[TM][TN];
#pragma unroll
    for (int i = 0; i < TM; i++)
#pragma unroll
        for (int j = 0; j < TN; j++) acc[i][j] = 0.0f;

    // Tile-fill assignment: 512 float4 per tile, 2 per thread.
    const int ld_row = tid >> 2;          // 0..63 (+64 on second pass)
    const int ld_k4  = (tid & 3) * 4;     // k offset within BK

    const int kTiles = K_ / BK;           // 128
    for (int kt = 0; kt < kTiles; ++kt) {
        const int kb = kt * BK;
        const float* asrc = (kb < D_) ? X : AV;
        const int akb = (kb < D_) ? kb : (kb - D_);

        // --- A tile: [BK][BM], source rows are n = row0 + row ---
#pragma unroll
        for (int r = 0; r < 2; ++r) {
            int row = ld_row + r * 64;
            float4 v = *reinterpret_cast<const float4*>(
                asrc + (size_t)(row0 + row) * D_ + akb + ld_k4);
            As[ld_k4 + 0][row] = v.x;
            As[ld_k4 + 1][row] = v.y;
            As[ld_k4 + 2][row] = v.z;
            As[ld_k4 + 3][row] = v.w;
        }
        // --- B tile: [BK][BN], W rows o and o+1024 interleaved by halves ---
#pragma unroll
        for (int r = 0; r < 2; ++r) {
            int c = ld_row + r * 64;
            int o = (c < 64) ? (bn * 64 + c) : (D_ + bn * 64 + (c - 64));
            float4 v = *reinterpret_cast<const float4*>(
                W + (size_t)o * K_ + kb + ld_k4);
            Bs[ld_k4 + 0][c] = v.x;
            Bs[ld_k4 + 1][c] = v.y;
            Bs[ld_k4 + 2][c] = v.z;
            Bs[ld_k4 + 3][c] = v.w;
        }
        __syncthreads();

#pragma unroll
        for (int k = 0; k < BK; ++k) {
            float a[TM], bv[TN];
#pragma unroll
            for (int i = 0; i < TM; i++) a[i] = As[k][ty * TM + i];
#pragma unroll
            for (int j = 0; j < 4; j++) bv[j]     = Bs[k][tx * 4 + j];
#pragma unroll
            for (int j = 0; j < 4; j++) bv[4 + j] = Bs[k][64 + tx * 4 + j];
#pragma unroll
            for (int i = 0; i < TM; i++)
#pragma unroll
                for (int j = 0; j < TN; j++)
                    acc[i][j] = fmaf(a[i], bv[j], acc[i][j]);
        }
        __syncthreads();
    }

    // --- fused epilogue ---
    const int d0 = bn * 64 + tx * 4;
    float bin[4], bfg[4];
#pragma unroll
    for (int j = 0; j < 4; j++) {
        bin[j] = bias[d0 + j];
        bfg[j] = bias[D_ + d0 + j];
    }

#pragma unroll
    for (int i = 0; i < TM; i++) {
        int n = row0 + ty * TM + i;
        float4 xv = *reinterpret_cast<const float4*>(X  + (size_t)n * D_ + d0);
        float4 av = *reinterpret_cast<const float4*>(AV + (size_t)n * D_ + d0);
        float4 o;
        o.x = sigmoidf_(acc[i][0] + bin[0]) * xv.x + sigmoidf_(acc[i][4] + bfg[0]) * av.x;
        o.y = sigmoidf_(acc[i][1] + bin[1]) * xv.y + sigmoidf_(acc[i][5] + bfg[1]) * av.y;
        o.z = sigmoidf_(acc[i][2] + bin[2]) * xv.z + sigmoidf_(acc[i][6] + bfg[2]) * av.z;
        o.w = sigmoidf_(acc[i][3] + bin[3]) * xv.w + sigmoidf_(acc[i][7] + bfg[3]) * av.w;
        *reinterpret_cast<float4*>(out + (size_t)n * D_ + d0) = o;
    }
}

// ---------------------------------------------------------------------------
// d_in: [0] inputs (B,L,D) f32, [1] W_gate (2D,2D) f32, [2] b_gate (2D) f32
// d_out: [gating_outputs (B,L,D) | average_outputs (B,L,D)] f32
// ---------------------------------------------------------------------------
extern "C" void kernel_launch(void* const* d_in, const int* in_sizes, int n_in,
                              void* d_out, int out_size) {
    (void)in_sizes; (void)n_in; (void)out_size;
    const float* X    = (const float*)d_in[0];
    const float* W    = (const float*)d_in[1];
    const float* bias = (const float*)d_in[2];

    float* gating = (float*)d_out;
    float* avg    = (float*)d_out + (size_t)NTOT * D_;

    // Pass 1: cumulative average written directly into the second output slot.
    cumavg_kernel<<<(B_ * D_) / 64, 64>>>(X, avg);

    // Pass 2: fused GEMM + sigmoid gating (reads avg produced above).
    dim3 grid(D_ / 64, NTOT / BM);
    gate_gemm_kernel<<<grid, 256>>>(X, avg, W, bias, gating);
}

// round 2
// speedup vs baseline: 1.9214x; 1.9214x over previous
#include <cuda_runtime.h>
#include <cstdint>

#define B_ 8
#define L_ 2048
#define D_ 1024
#define NTOT (B_ * L_)       /* 16384 rows */
#define K_ (2 * D_)          /* 2048 reduction dim */

#define BM 128
#define BN 128               /* interleaved: even col = in-gate, odd = fg-gate */
#define BK 16
#define BKP 20               /* padded k-stride: conflict-free + 16B aligned   */
#define KTILES (K_ / BK)     /* 128 */

__device__ __forceinline__ float sigmoidf_(float x) {
    return 1.0f / (1.0f + __expf(-x));
}

__device__ __forceinline__ uint32_t f2tf32(float f) {
    uint32_t u;
    asm("cvt.rna.tf32.f32 %0, %1;" : "=r"(u) : "f"(f));
    return u;
}

__device__ __forceinline__ void mma_tf32(float* c, const uint32_t* a, const uint32_t* b) {
    asm volatile(
        "mma.sync.aligned.m16n8k8.row.col.f32.tf32.tf32.f32 "
        "{%0,%1,%2,%3}, {%4,%5,%6,%7}, {%8,%9}, {%0,%1,%2,%3};"
        : "+f"(c[0]), "+f"(c[1]), "+f"(c[2]), "+f"(c[3])
        : "r"(a[0]), "r"(a[1]), "r"(a[2]), "r"(a[3]), "r"(b[0]), "r"(b[1]));
}

__device__ __forceinline__ void cp_async16(float* s, const float* g) {
    uint32_t sa = (uint32_t)__cvta_generic_to_shared(s);
    asm volatile("cp.async.cg.shared.global [%0], [%1], 16;" :: "r"(sa), "l"(g));
}
__device__ __forceinline__ void cp_commit() {
    asm volatile("cp.async.commit_group;");
}
template <int N>
__device__ __forceinline__ void cp_wait() {
    asm volatile("cp.async.wait_group %0;" :: "n"(N));
}

// ---------------------------------------------------------------------------
// Kernel 1: cumulative average (unchanged — coalesced column scan).
// ---------------------------------------------------------------------------
__global__ void cumavg_kernel(const float* __restrict__ x, float* __restrict__ avg) {
    int col = blockIdx.x * blockDim.x + threadIdx.x;   // 0 .. B*D-1
    int b = col >> 10;
    int d = col & (D_ - 1);
    const float* xp = x + (size_t)b * L_ * D_ + d;
    float* ap = avg + (size_t)b * L_ * D_ + d;
    float sum = 0.0f;
#pragma unroll 8
    for (int t = 0; t < L_; ++t) {
        sum += __ldg(xp + (size_t)t * D_);
        ap[(size_t)t * D_] = sum / (float)(t + 1);
    }
}

// ---------------------------------------------------------------------------
// Kernel 2: tf32 tensor-core GEMM + fused sigmoid gating.
//   g[n, o] = sum_k cat[n,k] * W[o,k] + bias[o]
// B-tile column n: n = 2c + gate, dim d = bn*64 + c, W row = gate*1024 + d.
// m16n8k8 accumulators: thread lane holds (c0,c1) = (g_in(d), g_fg(d)) for
// one d -> epilogue is register-local.
// ---------------------------------------------------------------------------
__global__ __launch_bounds__(256)
void gate_gemm_tc(const float* __restrict__ X,
                  const float* __restrict__ AV,
                  const float* __restrict__ W,
                  const float* __restrict__ bias,
                  float* __restrict__ out)
{
    __shared__ float As[2][BM][BKP];   // 20 KB
    __shared__ float Bs[2][BN][BKP];   // 20 KB

    const int tid    = threadIdx.x;
    const int lane   = tid & 31;
    const int wid    = tid >> 5;         // 0..7
    const int warp_m = wid & 3;          // 4 warps along M (32 rows each)
    const int warp_n = wid >> 2;         // 2 warps along N (64 cols each)
    const int lr     = lane >> 2;        // 0..7
    const int lc     = lane & 3;         // 0..3

    const int bn   = blockIdx.x;         // 0..15 -> dims [bn*64, bn*64+64)
    const int bm   = blockIdx.y;         // 0..127
    const int row0 = bm * BM;
    const int d0   = bn * 64;

    float acc[2][8][4];
#pragma unroll
    for (int i = 0; i < 2; i++)
#pragma unroll
        for (int j = 0; j < 8; j++)
#pragma unroll
            for (int r = 0; r < 4; r++) acc[i][j][r] = 0.0f;

    // ---- async tile loader: 512 float4 per tile, 2 per thread per tile ----
    auto load_tiles = [&](int kt, int stg) {
        const int kb = kt * BK;
        const float* asrc = (kb < D_) ? X : AV;
        const int akb = (kb < D_) ? kb : (kb - D_);
#pragma unroll
        for (int j = 0; j < 2; ++j) {
            int idx = tid + 256 * j;
            int row = idx >> 2;
            int k4  = (idx & 3) * 4;
            cp_async16(&As[stg][row][k4],
                       asrc + (size_t)(row0 + row) * D_ + akb + k4);
        }
#pragma unroll
        for (int j = 0; j < 2; ++j) {
            int idx = tid + 256 * j;
            int n  = idx >> 2;
            int k4 = (idx & 3) * 4;
            int c  = n >> 1;
            int g  = n & 1;
            int o  = g * D_ + d0 + c;
            cp_async16(&Bs[stg][n][k4],
                       W + (size_t)o * K_ + kb + k4);
        }
        cp_commit();
    };

    load_tiles(0, 0);

    for (int kt = 0; kt < KTILES; ++kt) {
        if (kt + 1 < KTILES) {
            load_tiles(kt + 1, (kt + 1) & 1);
            cp_wait<1>();
        } else {
            cp_wait<0>();
        }
        __syncthreads();

        const int st = kt & 1;
#pragma unroll
        for (int ks = 0; ks < 2; ++ks) {
            const int k0 = ks * 8;
            uint32_t aR[2][4];
            uint32_t bR[8][2];
#pragma unroll
            for (int mt = 0; mt < 2; ++mt) {
                int rb = warp_m * 32 + mt * 16 + lr;
                aR[mt][0] = f2tf32(As[st][rb][k0 + lc]);
                aR[mt][1] = f2tf32(As[st][rb + 8][k0 + lc]);
                aR[mt][2] = f2tf32(As[st][rb][k0 + lc + 4]);
                aR[mt][3] = f2tf32(As[st][rb + 8][k0 + lc + 4]);
            }
#pragma unroll
            for (int nt = 0; nt < 8; ++nt) {
                int n = warp_n * 64 + nt * 8 + lr;
                bR[nt][0] = f2tf32(Bs[st][n][k0 + lc]);
                bR[nt][1] = f2tf32(Bs[st][n][k0 + lc + 4]);
            }
#pragma unroll
            for (int mt = 0; mt < 2; ++mt)
#pragma unroll
                for (int nt = 0; nt < 8; ++nt)
                    mma_tf32(acc[mt][nt], aR[mt], bR[nt]);
        }
        __syncthreads();
    }

    // ---- fused epilogue: out = sig(g_in)*x + sig(g_fg)*avg ----
#pragma unroll
    for (int mt = 0; mt < 2; ++mt) {
#pragma unroll
        for (int nt = 0; nt < 8; ++nt) {
            int d = d0 + warp_n * 32 + nt * 4 + lc;
            float bin = bias[d];
            float bfg = bias[D_ + d];

            int row = row0 + warp_m * 32 + mt * 16 + lr;
            {
                size_t off = (size_t)row * D_ + d;
                float gin = acc[mt][nt][0] + bin;
                float gfg = acc[mt][nt][1] + bfg;
                out[off] = sigmoidf_(gin) * X[off] + sigmoidf_(gfg) * AV[off];
            }
            {
                size_t off = (size_t)(row + 8) * D_ + d;
                float gin = acc[mt][nt][2] + bin;
                float gfg = acc[mt][nt][3] + bfg;
                out[off] = sigmoidf_(gin) * X[off] + sigmoidf_(gfg) * AV[off];
            }
        }
    }
}

// ---------------------------------------------------------------------------
// d_in: [0] inputs (B,L,D) f32, [1] W_gate (2D,2D) f32, [2] b_gate (2D) f32
// d_out: [gating_outputs (B,L,D) | average_outputs (B,L,D)] f32
// ---------------------------------------------------------------------------
extern "C" void kernel_launch(void* const* d_in, const int* in_sizes, int n_in,
                              void* d_out, int out_size) {
    (void)in_sizes; (void)n_in; (void)out_size;
    const float* X    = (const float*)d_in[0];
    const float* W    = (const float*)d_in[1];
    const float* bias = (const float*)d_in[2];

    float* gating = (float*)d_out;
    float* avg    = (float*)d_out + (size_t)NTOT * D_;

    cumavg_kernel<<<(B_ * D_) / 64, 64>>>(X, avg);

    dim3 grid(D_ / 64, NTOT / BM);
    gate_gemm_tc<<<grid, 256>>>(X, avg, W, bias, gating);
}

// round 5
// speedup vs baseline: 3.3447x; 1.7408x over previous
#include <cuda_runtime.h>
#include <cstdint>

#define B_ 8
#define L_ 2048
#define D_ 1024
#define NTOT (B_ * L_)       /* 16384 rows */
#define K_ (2 * D_)          /* 2048 reduction dim */

#define BM 256               /* rows per CTA */
#define BN 128               /* interleaved: even col = in-gate, odd = fg-gate (64 dims) */
#define BK 16
#define BKP 20               /* padded k-stride: conflict-free + 16B aligned */
#define STAGES 3
#define KTILES (K_ / BK)     /* 128 */

/* dynamic smem layout (floats):
   As[stg][row][k] : stg*BM*BKP + row*BKP + k     (3*256*20 = 15360 floats)
   Bs[stg][n][k]   : AOFF + stg*BN*BKP + n*BKP+k  (3*128*20 =  7680 floats) */
#define A_FLOATS (STAGES * BM * BKP)
#define SMEM_FLOATS (A_FLOATS + STAGES * BN * BKP)
#define SMEM_BYTES (SMEM_FLOATS * 4)   /* 92160 */

__device__ __forceinline__ float sigmoidf_(float x) {
    return 1.0f / (1.0f + __expf(-x));
}

__device__ __forceinline__ void mma_tf32(float* c, const uint32_t* a, const uint32_t* b) {
    asm volatile(
        "mma.sync.aligned.m16n8k8.row.col.f32.tf32.tf32.f32 "
        "{%0,%1,%2,%3}, {%4,%5,%6,%7}, {%8,%9}, {%0,%1,%2,%3};"
        : "+f"(c[0]), "+f"(c[1]), "+f"(c[2]), "+f"(c[3])
        : "r"(a[0]), "r"(a[1]), "r"(a[2]), "r"(a[3]), "r"(b[0]), "r"(b[1]));
}

__device__ __forceinline__ void cp_async16(float* s, const float* g) {
    uint32_t sa = (uint32_t)__cvta_generic_to_shared(s);
    asm volatile("cp.async.cg.shared.global [%0], [%1], 16;" :: "r"(sa), "l"(g));
}
__device__ __forceinline__ void cp_commit() {
    asm volatile("cp.async.commit_group;");
}
template <int N>
__device__ __forceinline__ void cp_wait() {
    asm volatile("cp.async.wait_group %0;" :: "n"(N));
}

/* ======================= cumulative average (2-pass chunked) ============ */
#define CHUNK 64
#define NCH (L_ / CHUNK)   /* 32 */
__device__ float g_part[B_ * NCH * D_];

__global__ void cumavg_part(const float* __restrict__ x) {
    int bc = blockIdx.x;            // 0..255
    int b = bc >> 5, c = bc & 31;
    int t0 = c * CHUNK;
    for (int d = threadIdx.x; d < D_; d += 256) {
        const float* p = x + ((size_t)b * L_ + t0) * D_ + d;
        float s = 0.0f;
#pragma unroll 8
        for (int t = 0; t < CHUNK; ++t) s += p[(size_t)t * D_];
        g_part[(b * NCH + c) * D_ + d] = s;
    }
}

__global__ void cumavg_scan(const float* __restrict__ x, float* __restrict__ avg) {
    int bc = blockIdx.x;
    int b = bc >> 5, c = bc & 31;
    int t0 = c * CHUNK;
    for (int d = threadIdx.x; d < D_; d += 256) {
        float run = 0.0f;
        for (int cc = 0; cc < c; ++cc) run += g_part[(b * NCH + cc) * D_ + d];
        const float* p = x + ((size_t)b * L_ + t0) * D_ + d;
        float* q = avg + ((size_t)b * L_ + t0) * D_ + d;
#pragma unroll 4
        for (int t = 0; t < CHUNK; ++t) {
            run += p[(size_t)t * D_];
            q[(size_t)t * D_] = run / (float)(t0 + t + 1);
        }
    }
}

/* ======================= tf32 tensor GEMM + fused gating ================ */
/* 8 warps, warp grid 4(m) x 2(n), warp tile 64x64.
   B column n = 2c + gate; dim d = bn*64 + c; W row = gate*1024 + d.
   Per-thread c-fragment cols (2lc, 2lc+1) = (g_in(d), g_fg(d)) for one d. */
__global__ __launch_bounds__(256, 1)
void gate_gemm_tc(const float* __restrict__ X,
                  const float* __restrict__ AV,
                  const float* __restrict__ W,
                  const float* __restrict__ bias,
                  float* __restrict__ out)
{
    extern __shared__ float smem[];
    float* Asm = smem;                 /* [STAGES][BM][BKP] */
    float* Bsm = smem + A_FLOATS;      /* [STAGES][BN][BKP] */

    const int tid    = threadIdx.x;
    const int lane   = tid & 31;
    const int wid    = tid >> 5;         // 0..7
    const int warp_m = wid & 3;          // 4 warps along M (64 rows each)
    const int warp_n = wid >> 2;         // 2 warps along N (64 cols each)
    const int lr     = lane >> 2;        // 0..7
    const int lc     = lane & 3;         // 0..3

    const int bn   = blockIdx.x;         // 0..15 -> dims [bn*64, bn*64+64)
    const int bm   = blockIdx.y;         // 0..63
    const int row0 = bm * BM;
    const int d0   = bn * 64;

    float acc[4][8][4];
#pragma unroll
    for (int i = 0; i < 4; i++)
#pragma unroll
        for (int j = 0; j < 8; j++)
#pragma unroll
            for (int r = 0; r < 4; r++) acc[i][j][r] = 0.0f;

    /* ---- async tile loader: A = 1024 f4 (4/thread), B = 512 f4 (2/thread) */
    auto load_tiles = [&](int kt, int stg) {
        const int kb = kt * BK;
        const float* asrc = (kb < D_) ? X : AV;
        const int akb = (kb < D_) ? kb : (kb - D_);
        float* As = Asm + stg * (BM * BKP);
        float* Bs = Bsm + stg * (BN * BKP);
#pragma unroll
        for (int j = 0; j < 4; ++j) {
            int idx = tid + 256 * j;
            int row = idx >> 2;
            int k4  = (idx & 3) * 4;
            cp_async16(As + row * BKP + k4,
                       asrc + (size_t)(row0 + row) * D_ + akb + k4);
        }
#pragma unroll
        for (int j = 0; j < 2; ++j) {
            int idx = tid + 256 * j;
            int n  = idx >> 2;
            int k4 = (idx & 3) * 4;
            int c  = n >> 1;
            int g  = n & 1;
            int o  = g * D_ + d0 + c;
            cp_async16(Bs + n * BKP + k4,
                       W + (size_t)o * K_ + kb + k4);
        }
        cp_commit();
    };

    load_tiles(0, 0);
    load_tiles(1, 1);

    for (int kt = 0; kt < KTILES; ++kt) {
        if (kt + 2 < KTILES) {
            load_tiles(kt + 2, (kt + 2) % STAGES);
            cp_wait<2>();
        } else if (kt + 1 < KTILES) {
            cp_wait<1>();
        } else {
            cp_wait<0>();
        }
        __syncthreads();

        const int st = kt % STAGES;
        const float* As = Asm + st * (BM * BKP);
        const float* Bs = Bsm + st * (BN * BKP);
#pragma unroll
        for (int ks = 0; ks < 2; ++ks) {
            const int k0 = ks * 8;
            uint32_t aR[4][4];
            uint32_t bR[8][2];
#pragma unroll
            for (int mt = 0; mt < 4; ++mt) {
                int rb = warp_m * 64 + mt * 16 + lr;
                aR[mt][0] = __float_as_uint(As[rb * BKP + k0 + lc]);
                aR[mt][1] = __float_as_uint(As[(rb + 8) * BKP + k0 + lc]);
                aR[mt][2] = __float_as_uint(As[rb * BKP + k0 + lc + 4]);
                aR[mt][3] = __float_as_uint(As[(rb + 8) * BKP + k0 + lc + 4]);
            }
#pragma unroll
            for (int nt = 0; nt < 8; ++nt) {
                int n = warp_n * 64 + nt * 8 + lr;
                bR[nt][0] = __float_as_uint(Bs[n * BKP + k0 + lc]);
                bR[nt][1] = __float_as_uint(Bs[n * BKP + k0 + lc + 4]);
            }
#pragma unroll
            for (int mt = 0; mt < 4; ++mt)
#pragma unroll
                for (int nt = 0; nt < 8; ++nt)
                    mma_tf32(acc[mt][nt], aR[mt], bR[nt]);
        }
        __syncthreads();
    }

    /* ---- fused epilogue: out = sig(g_in)*x + sig(g_fg)*avg ---- */
#pragma unroll
    for (int mt = 0; mt < 4; ++mt) {
#pragma unroll
        for (int nt = 0; nt < 8; ++nt) {
            int d = d0 + warp_n * 32 + nt * 4 + lc;
            float bin = __ldg(&bias[d]);
            float bfg = __ldg(&bias[D_ + d]);

            int row = row0 + warp_m * 64 + mt * 16 + lr;
            {
                size_t off = (size_t)row * D_ + d;
                float gin = acc[mt][nt][0] + bin;
                float gfg = acc[mt][nt][1] + bfg;
                out[off] = sigmoidf_(gin) * X[off] + sigmoidf_(gfg) * AV[off];
            }
            {
                size_t off = (size_t)(row + 8) * D_ + d;
                float gin = acc[mt][nt][2] + bin;
                float gfg = acc[mt][nt][3] + bfg;
                out[off] = sigmoidf_(gin) * X[off] + sigmoidf_(gfg) * AV[off];
            }
        }
    }
}

/* ======================= host ======================= */
extern "C" void kernel_launch(void* const* d_in, const int* in_sizes, int n_in,
                              void* d_out, int out_size) {
    (void)in_sizes; (void)n_in; (void)out_size;
    const float* X    = (const float*)d_in[0];
    const float* W    = (const float*)d_in[1];
    const float* bias = (const float*)d_in[2];

    float* gating = (float*)d_out;
    float* avg    = (float*)d_out + (size_t)NTOT * D_;

    static bool attr_set = false;
    if (!attr_set) {
        cudaFuncSetAttribute(gate_gemm_tc,
                             cudaFuncAttributeMaxDynamicSharedMemorySize, SMEM_BYTES);
        attr_set = true;
    }

    cumavg_part<<<B_ * NCH, 256>>>(X);
    cumavg_scan<<<B_ * NCH, 256>>>(X, avg);

    dim3 grid(D_ / 64, NTOT / BM);   /* (16, 64) */
    gate_gemm_tc<<<grid, 256, SMEM_BYTES>>>(X, avg, W, bias, gating);
}

// round 6
// speedup vs baseline: 5.1084x; 1.5273x over previous
#include <cuda_runtime.h>
#include <cuda_fp16.h>
#include <cstdint>

#define B_ 8
#define L_ 2048
#define D_ 1024
#define NTOT (B_ * L_)       /* 16384 rows */
#define K_ (2 * D_)          /* 2048 reduction dim */

#define BM 256               /* rows per CTA */
#define BN 128               /* interleaved: even col = in-gate, odd = fg-gate */
#define BK 32                /* fp16 k per stage */
#define PITCH 40             /* halves per row: 80B, 16B-aligned, conflict-free */
#define STAGES 4
#define KTILES (K_ / BK)     /* 64 */

#define A_HALVES (STAGES * BM * PITCH)
#define SMEM_HALVES (A_HALVES + STAGES * BN * PITCH)
#define SMEM_BYTES (SMEM_HALVES * 2)   /* 122880 */

/* fp16 scratch (device globals -- no allocation) */
__device__ __half h_X[NTOT * D_];     /* 32 MB */
__device__ __half h_AV[NTOT * D_];    /* 32 MB */
__device__ __half h_W[K_ * K_];       /* 8 MB  */

__device__ __forceinline__ float sigmoidf_(float x) {
    return 1.0f / (1.0f + __expf(-x));
}

__device__ __forceinline__ void mma_f16(float* c, const uint32_t* a, const uint32_t* b) {
    asm volatile(
        "mma.sync.aligned.m16n8k16.row.col.f32.f16.f16.f32 "
        "{%0,%1,%2,%3}, {%4,%5,%6,%7}, {%8,%9}, {%0,%1,%2,%3};"
        : "+f"(c[0]), "+f"(c[1]), "+f"(c[2]), "+f"(c[3])
        : "r"(a[0]), "r"(a[1]), "r"(a[2]), "r"(a[3]), "r"(b[0]), "r"(b[1]));
}

__device__ __forceinline__ void cp_async16(__half* s, const __half* g) {
    uint32_t sa = (uint32_t)__cvta_generic_to_shared(s);
    asm volatile("cp.async.cg.shared.global [%0], [%1], 16;" :: "r"(sa), "l"(g));
}
__device__ __forceinline__ void cp_commit() {
    asm volatile("cp.async.commit_group;");
}
template <int N>
__device__ __forceinline__ void cp_wait() {
    asm volatile("cp.async.wait_group %0;" :: "n"(N));
}

/* ======================= f32 -> f16 conversion ======================= */
__global__ void cvt_f16(const float* __restrict__ src, __half* __restrict__ dst, int n4) {
    int i = blockIdx.x * blockDim.x + threadIdx.x;
    if (i < n4) {
        float4 v = reinterpret_cast<const float4*>(src)[i];
        __half2 lo = __floats2half2_rn(v.x, v.y);
        __half2 hi = __floats2half2_rn(v.z, v.w);
        reinterpret_cast<__half2*>(dst)[i * 2]     = lo;
        reinterpret_cast<__half2*>(dst)[i * 2 + 1] = hi;
    }
}

/* ======================= cumulative average (2-pass chunked) ============ */
#define CHUNK 64
#define NCH (L_ / CHUNK)   /* 32 */
__device__ float g_part[B_ * NCH * D_];

__global__ void cumavg_part(const float* __restrict__ x) {
    int bc = blockIdx.x;            // 0..255
    int b = bc >> 5, c = bc & 31;
    int t0 = c * CHUNK;
    for (int d = threadIdx.x; d < D_; d += 256) {
        const float* p = x + ((size_t)b * L_ + t0) * D_ + d;
        float s = 0.0f;
#pragma unroll 8
        for (int t = 0; t < CHUNK; ++t) s += p[(size_t)t * D_];
        g_part[(b * NCH + c) * D_ + d] = s;
    }
}

__global__ void cumavg_scan(const float* __restrict__ x, float* __restrict__ avg) {
    int bc = blockIdx.x;
    int b = bc >> 5, c = bc & 31;
    int t0 = c * CHUNK;
    for (int d = threadIdx.x; d < D_; d += 256) {
        float run = 0.0f;
        for (int cc = 0; cc < c; ++cc) run += g_part[(b * NCH + cc) * D_ + d];
        const float* p = x + ((size_t)b * L_ + t0) * D_ + d;
        size_t base = ((size_t)b * L_ + t0) * D_ + d;
#pragma unroll 4
        for (int t = 0; t < CHUNK; ++t) {
            run += p[(size_t)t * D_];
            float a = run / (float)(t0 + t + 1);
            avg[base + (size_t)t * D_] = a;
            h_AV[base + (size_t)t * D_] = __float2half_rn(a);
        }
    }
}

/* ======================= fp16 tensor GEMM + fused gating ================ */
/* 8 warps, warp grid 4(m) x 2(n), warp tile 64x64.
   B column n = 2c + gate; dim d = bn*64 + c; W row = gate*1024 + d.
   m16n8k16 c-frag: (c0,c1) = cols (2lc, 2lc+1) = (g_in(d), g_fg(d)). */
__global__ __launch_bounds__(256, 1)
void gate_gemm_f16(const float* __restrict__ X,
                   const float* __restrict__ AV,
                   const float* __restrict__ bias,
                   float* __restrict__ out)
{
    extern __shared__ __half smem[];
    __half* Asm = smem;                  /* [STAGES][BM][PITCH] */
    __half* Bsm = smem + A_HALVES;       /* [STAGES][BN][PITCH] */

    const int tid    = threadIdx.x;
    const int lane   = tid & 31;
    const int wid    = tid >> 5;         // 0..7
    const int warp_m = wid & 3;          // 4 warps along M (64 rows each)
    const int warp_n = wid >> 2;         // 2 warps along N (64 cols each)
    const int lr     = lane >> 2;        // 0..7  (group id)
    const int lc     = lane & 3;         // 0..3  (thread in group)

    const int bn   = blockIdx.x;         // 0..15 -> dims [bn*64, bn*64+64)
    const int bm   = blockIdx.y;         // 0..63
    const int row0 = bm * BM;
    const int d0   = bn * 64;

    float acc[4][8][4];
#pragma unroll
    for (int i = 0; i < 4; i++)
#pragma unroll
        for (int j = 0; j < 8; j++)
#pragma unroll
            for (int r = 0; r < 4; r++) acc[i][j][r] = 0.0f;

    /* ---- async tile loader: rows of 32 halves = 64B = 4x16B chunks.
       A: 1024 chunks (4/thread), B: 512 chunks (2/thread). ---- */
    auto load_tiles = [&](int kt, int stg) {
        const int kb = kt * BK;
        const __half* asrc = (kb < D_) ? h_X : h_AV;
        const int akb = (kb < D_) ? kb : (kb - D_);
        __half* As = Asm + stg * (BM * PITCH);
        __half* Bs = Bsm + stg * (BN * PITCH);
#pragma unroll
        for (int j = 0; j < 4; ++j) {
            int idx = tid + 256 * j;
            int row = idx >> 2;
            int off = (idx & 3) * 8;          /* halves */
            cp_async16(As + row * PITCH + off,
                       asrc + (size_t)(row0 + row) * D_ + akb + off);
        }
#pragma unroll
        for (int j = 0; j < 2; ++j) {
            int idx = tid + 256 * j;
            int n   = idx >> 2;
            int off = (idx & 3) * 8;
            int c = n >> 1;
            int g = n & 1;
            int o = g * D_ + d0 + c;
            cp_async16(Bs + n * PITCH + off,
                       h_W + (size_t)o * K_ + kb + off);
        }
        cp_commit();
    };

    load_tiles(0, 0);
    load_tiles(1, 1);
    load_tiles(2, 2);

    for (int kt = 0; kt < KTILES; ++kt) {
        if (kt + 3 < KTILES) {
            load_tiles(kt + 3, (kt + 3) % STAGES);
            cp_wait<3>();
        } else if (kt + 2 < KTILES) {
            cp_wait<2>();
        } else if (kt + 1 < KTILES) {
            cp_wait<1>();
        } else {
            cp_wait<0>();
        }
        __syncthreads();

        const int st = kt % STAGES;
        const __half* As = Asm + st * (BM * PITCH);
        const __half* Bs = Bsm + st * (BN * PITCH);

#pragma unroll
        for (int ks = 0; ks < 2; ++ks) {
            const int k0 = ks * 16;
            uint32_t aR[4][4];
            uint32_t bR[8][2];
            /* A m16k16 frag: a0=(lr, 2lc) a1=(lr+8, 2lc) a2=(lr, 2lc+8) a3=(lr+8, 2lc+8) */
#pragma unroll
            for (int mt = 0; mt < 4; ++mt) {
                int rb = warp_m * 64 + mt * 16 + lr;
                const __half* p0 = As + rb * PITCH + k0 + 2 * lc;
                const __half* p1 = As + (rb + 8) * PITCH + k0 + 2 * lc;
                aR[mt][0] = *reinterpret_cast<const uint32_t*>(p0);
                aR[mt][1] = *reinterpret_cast<const uint32_t*>(p1);
                aR[mt][2] = *reinterpret_cast<const uint32_t*>(p0 + 8);
                aR[mt][3] = *reinterpret_cast<const uint32_t*>(p1 + 8);
            }
            /* B k16n8 frag (col): b0=(k=2lc, n=lr) b1=(k=2lc+8, n=lr); Bs is [n][k] */
#pragma unroll
            for (int nt = 0; nt < 8; ++nt) {
                int n = warp_n * 64 + nt * 8 + lr;
                const __half* p = Bs + n * PITCH + k0 + 2 * lc;
                bR[nt][0] = *reinterpret_cast<const uint32_t*>(p);
                bR[nt][1] = *reinterpret_cast<const uint32_t*>(p + 8);
            }
#pragma unroll
            for (int mt = 0; mt < 4; ++mt)
#pragma unroll
                for (int nt = 0; nt < 8; ++nt)
                    mma_f16(acc[mt][nt], aR[mt], bR[nt]);
        }
        __syncthreads();
    }

    /* ---- fused epilogue: out = sig(g_in)*x + sig(g_fg)*avg ---- */
#pragma unroll
    for (int mt = 0; mt < 4; ++mt) {
#pragma unroll
        for (int nt = 0; nt < 8; ++nt) {
            int d = d0 + warp_n * 32 + nt * 4 + lc;
            float bin = __ldg(&bias[d]);
            float bfg = __ldg(&bias[D_ + d]);

            int row = row0 + warp_m * 64 + mt * 16 + lr;
            {
                size_t off = (size_t)row * D_ + d;
                float gin = acc[mt][nt][0] + bin;
                float gfg = acc[mt][nt][1] + bfg;
                out[off] = sigmoidf_(gin) * X[off] + sigmoidf_(gfg) * AV[off];
            }
            {
                size_t off = (size_t)(row + 8) * D_ + d;
                float gin = acc[mt][nt][2] + bin;
                float gfg = acc[mt][nt][3] + bfg;
                out[off] = sigmoidf_(gin) * X[off] + sigmoidf_(gfg) * AV[off];
            }
        }
    }
}

/* ======================= host ======================= */
extern "C" void kernel_launch(void* const* d_in, const int* in_sizes, int n_in,
                              void* d_out, int out_size) {
    (void)in_sizes; (void)n_in; (void)out_size;
    const float* X    = (const float*)d_in[0];
    const float* W    = (const float*)d_in[1];
    const float* bias = (const float*)d_in[2];

    float* gating = (float*)d_out;
    float* avg    = (float*)d_out + (size_t)NTOT * D_;

    static bool attr_set = false;
    if (!attr_set) {
        cudaFuncSetAttribute(gate_gemm_f16,
                             cudaFuncAttributeMaxDynamicSharedMemorySize, SMEM_BYTES);
        attr_set = true;
    }

    __half* dX; cudaGetSymbolAddress((void**)&dX, h_X);
    __half* dW; cudaGetSymbolAddress((void**)&dW, h_W);

    /* conversions + cumavg (avg's f16 copy fused into the scan) */
    cvt_f16<<<(NTOT * D_ / 4 + 255) / 256, 256>>>(X, dX, NTOT * D_ / 4);
    cvt_f16<<<(K_ * K_ / 4 + 255) / 256, 256>>>(W, dW, K_ * K_ / 4);
    cumavg_part<<<B_ * NCH, 256>>>(X);
    cumavg_scan<<<B_ * NCH, 256>>>(X, avg);

    dim3 grid(D_ / 64, NTOT / BM);   /* (16, 64) */
    gate_gemm_f16<<<grid, 256, SMEM_BYTES>>>(X, avg, bias, gating);
}

// round 7
// speedup vs baseline: 6.2665x; 1.2267x over previous
#include <cuda_runtime.h>
#include <cuda_fp16.h>
#include <cstdint>

#define B_ 8
#define L_ 2048
#define D_ 1024
#define NTOT (B_ * L_)       /* 16384 rows */
#define K_ (2 * D_)          /* 2048 reduction dim */

#define BM 256               /* rows per CTA */
#define BN 128               /* cols: [0,64)=in-gate dims, [64,128)=fg-gate dims */
#define BK 32                /* fp16 k per stage */
#define PITCH 40             /* halves per row: 80B; rows hit disjoint bank groups */
#define STAGES 4
#define KTILES (K_ / BK)     /* 64 */

#define A_HALVES (STAGES * BM * PITCH)
#define SMEM_HALVES (A_HALVES + STAGES * BN * PITCH)
#define SMEM_BYTES (SMEM_HALVES * 2)   /* 122880 */

/* fp16 scratch (device globals -- no allocation) */
__device__ __half h_X[NTOT * D_];     /* 32 MB */
__device__ __half h_AV[NTOT * D_];    /* 32 MB */
__device__ __half h_W[K_ * K_];       /* 8 MB  */

__device__ __forceinline__ float sigmoidf_(float x) {
    return 1.0f / (1.0f + __expf(-x));
}

__device__ __forceinline__ void mma_f16(float* c, const uint32_t* a, const uint32_t* b) {
    asm volatile(
        "mma.sync.aligned.m16n8k16.row.col.f32.f16.f16.f32 "
        "{%0,%1,%2,%3}, {%4,%5,%6,%7}, {%8,%9}, {%0,%1,%2,%3};"
        : "+f"(c[0]), "+f"(c[1]), "+f"(c[2]), "+f"(c[3])
        : "r"(a[0]), "r"(a[1]), "r"(a[2]), "r"(a[3]), "r"(b[0]), "r"(b[1]));
}

__device__ __forceinline__ void ldsm_x4(uint32_t& r0, uint32_t& r1, uint32_t& r2,
                                        uint32_t& r3, uint32_t addr) {
    asm volatile("ldmatrix.sync.aligned.m8n8.x4.shared.b16 {%0,%1,%2,%3}, [%4];"
                 : "=r"(r0), "=r"(r1), "=r"(r2), "=r"(r3) : "r"(addr));
}

__device__ __forceinline__ void cp_async16(__half* s, const __half* g) {
    uint32_t sa = (uint32_t)__cvta_generic_to_shared(s);
    asm volatile("cp.async.cg.shared.global [%0], [%1], 16;" :: "r"(sa), "l"(g));
}
__device__ __forceinline__ void cp_commit() {
    asm volatile("cp.async.commit_group;");
}
template <int N>
__device__ __forceinline__ void cp_wait() {
    asm volatile("cp.async.wait_group %0;" :: "n"(N));
}

__device__ __forceinline__ uint2 pack_h4(float a, float b, float c, float d) {
    __half2 lo = __floats2half2_rn(a, b);
    __half2 hi = __floats2half2_rn(c, d);
    uint2 u;
    u.x = *reinterpret_cast<uint32_t*>(&lo);
    u.y = *reinterpret_cast<uint32_t*>(&hi);
    return u;
}

/* ======================= f32 -> f16 conversion (W only) ================ */
__global__ void cvt_f16(const float* __restrict__ src, __half* __restrict__ dst, int n4) {
    int i = blockIdx.x * blockDim.x + threadIdx.x;
    if (i < n4) {
        float4 v = reinterpret_cast<const float4*>(src)[i];
        reinterpret_cast<uint2*>(dst)[i] = pack_h4(v.x, v.y, v.z, v.w);
    }
}

/* ======================= cumulative average (3-pass, float4) =========== */
#define CHUNK 64
#define NCH (L_ / CHUNK)   /* 32 */
#define D4 (D_ / 4)        /* 256 */
__device__ float g_part[B_ * NCH * D_];

/* Pass 1: chunk sums + fused X -> fp16 conversion. grid 256, 256 thr. */
__global__ void cumavg_part_cvt(const float* __restrict__ x) {
    int b = blockIdx.x >> 5, c = blockIdx.x & 31;
    int d4 = threadIdx.x;
    size_t base = ((size_t)b * L_ + c * CHUNK) * D4 + d4;
    const float4* px = reinterpret_cast<const float4*>(x) + base;
    uint2* ph = reinterpret_cast<uint2*>(h_X) + base;
    float4 s = {0.f, 0.f, 0.f, 0.f};
#pragma unroll 8
    for (int t = 0; t < CHUNK; ++t) {
        float4 v = px[(size_t)t * D4];
        s.x += v.x; s.y += v.y; s.z += v.z; s.w += v.w;
        ph[(size_t)t * D4] = pack_h4(v.x, v.y, v.z, v.w);
    }
    reinterpret_cast<float4*>(g_part)[(b * NCH + c) * D4 + d4] = s;
}

/* Pass 2: exclusive prefix over the 32 chunk sums. 2048 threads. */
__global__ void chunk_prefix() {
    int idx = blockIdx.x * blockDim.x + threadIdx.x;   /* 0..2047 */
    int b = idx >> 8, d4 = idx & 255;
    float4* gp = reinterpret_cast<float4*>(g_part);
    float4 run = {0.f, 0.f, 0.f, 0.f};
#pragma unroll
    for (int c = 0; c < NCH; ++c) {
        float4 v = gp[(b * NCH + c) * D4 + d4];
        gp[(b * NCH + c) * D4 + d4] = run;
        run.x += v.x; run.y += v.y; run.z += v.z; run.w += v.w;
    }
}

/* Pass 3: scan + divide, writes avg f32 + h_AV fp16. grid 256, 256 thr. */
__global__ void cumavg_scan_v3(const float* __restrict__ x, float* __restrict__ avg) {
    int b = blockIdx.x >> 5, c = blockIdx.x & 31;
    int d4 = threadIdx.x;
    int t0 = c * CHUNK;
    float4 run = reinterpret_cast<const float4*>(g_part)[(b * NCH + c) * D4 + d4];
    size_t base = ((size_t)b * L_ + t0) * D4 + d4;
    const float4* px = reinterpret_cast<const float4*>(x) + base;
    float4* pa = reinterpret_cast<float4*>(avg) + base;
    uint2* ph = reinterpret_cast<uint2*>(h_AV) + base;
#pragma unroll 4
    for (int t = 0; t < CHUNK; ++t) {
        float4 v = px[(size_t)t * D4];
        run.x += v.x; run.y += v.y; run.z += v.z; run.w += v.w;
        float r = 1.0f / (float)(t0 + t + 1);
        float4 a = {run.x * r, run.y * r, run.z * r, run.w * r};
        pa[(size_t)t * D4] = a;
        ph[(size_t)t * D4] = pack_h4(a.x, a.y, a.z, a.w);
    }
}

/* ======================= fp16 tensor GEMM + fused gating ================ */
/* 8 warps, warp grid 4(m) x 2(n), warp tile 64x64 (32 in-gate + 32 fg cols).
   B col n<64: o = d0+n (in-gate); n>=64: o = D_+d0+(n-64) (fg-gate).
   Warp nt 0-3 -> in-gate cols warp_n*32+nt*8; nt 4-7 -> fg, same dims.
   c-frag (c0,c1) = cols (2lc, 2lc+1): contiguous d pair -> float2 epilogue. */
__global__ __launch_bounds__(256, 1)
void gate_gemm_f16(const float* __restrict__ X,
                   const float* __restrict__ AV,
                   const float* __restrict__ bias,
                   float* __restrict__ out)
{
    extern __shared__ __half smem[];
    __half* Asm = smem;                  /* [STAGES][BM][PITCH] */
    __half* Bsm = smem + A_HALVES;       /* [STAGES][BN][PITCH] */

    const int tid    = threadIdx.x;
    const int lane   = tid & 31;
    const int wid    = tid >> 5;
    const int warp_m = wid & 3;          /* 4 warps along M (64 rows each) */
    const int warp_n = wid >> 2;         /* 2 warps along N (32 dims each) */
    const int lr     = lane >> 2;
    const int lc     = lane & 3;

    const int bn   = blockIdx.x;         /* 0..15 -> dims [bn*64, bn*64+64) */
    const int bm   = blockIdx.y;         /* 0..63 */
    const int row0 = bm * BM;
    const int d0   = bn * 64;

    const uint32_t As_u32 = (uint32_t)__cvta_generic_to_shared(Asm);
    const uint32_t Bs_u32 = (uint32_t)__cvta_generic_to_shared(Bsm);

    /* per-lane ldmatrix offsets (halves) */
    const int a_lane = (lane & 15) * PITCH + (lane >> 4) * 8;
    const int b_lane = ((lane & 7) + ((lane >> 4) << 3)) * PITCH + (((lane >> 3) & 1) << 3);

    float acc[4][8][4];
#pragma unroll
    for (int i = 0; i < 4; i++)
#pragma unroll
        for (int j = 0; j < 8; j++)
#pragma unroll
            for (int r = 0; r < 4; r++) acc[i][j][r] = 0.0f;

    auto load_tiles = [&](int kt, int stg) {
        const int kb = kt * BK;
        const __half* asrc = (kb < D_) ? h_X : h_AV;
        const int akb = (kb < D_) ? kb : (kb - D_);
        __half* As = Asm + stg * (BM * PITCH);
        __half* Bs = Bsm + stg * (BN * PITCH);
#pragma unroll
        for (int j = 0; j < 4; ++j) {
            int idx = tid + 256 * j;
            int row = idx >> 2;
            int off = (idx & 3) * 8;
            cp_async16(As + row * PITCH + off,
                       asrc + (size_t)(row0 + row) * D_ + akb + off);
        }
#pragma unroll
        for (int j = 0; j < 2; ++j) {
            int idx = tid + 256 * j;
            int n   = idx >> 2;
            int off = (idx & 3) * 8;
            int o = (n < 64) ? (d0 + n) : (D_ + d0 + (n - 64));
            cp_async16(Bs + n * PITCH + off,
                       h_W + (size_t)o * K_ + kb + off);
        }
        cp_commit();
    };

    load_tiles(0, 0);
    load_tiles(1, 1);
    load_tiles(2, 2);

    for (int kt = 0; kt < KTILES; ++kt) {
        if (kt + 3 < KTILES) {
            load_tiles(kt + 3, (kt + 3) % STAGES);
            cp_wait<3>();
        } else if (kt + 2 < KTILES) {
            cp_wait<2>();
        } else if (kt + 1 < KTILES) {
            cp_wait<1>();
        } else {
            cp_wait<0>();
        }
        __syncthreads();

        const int st = kt % STAGES;
        const uint32_t a_base = As_u32 + 2 * (st * (BM * PITCH) + warp_m * 64 * PITCH + a_lane);
        const uint32_t b_base = Bs_u32 + 2 * (st * (BN * PITCH) + b_lane);

#pragma unroll
        for (int ks = 0; ks < 2; ++ks) {
            uint32_t aR[4][4];
            uint32_t bR[8][2];
#pragma unroll
            for (int mt = 0; mt < 4; ++mt)
                ldsm_x4(aR[mt][0], aR[mt][1], aR[mt][2], aR[mt][3],
                        a_base + 2 * (mt * 16 * PITCH + ks * 16));
#pragma unroll
            for (int ntp = 0; ntp < 4; ++ntp) {
                int nt = 2 * ntp;
                int fnt = (nt < 4) ? (warp_n * 32 + nt * 8)
                                   : (64 + warp_n * 32 + (nt - 4) * 8);
                ldsm_x4(bR[nt][0], bR[nt][1], bR[nt + 1][0], bR[nt + 1][1],
                        b_base + 2 * (fnt * PITCH + ks * 16));
            }
#pragma unroll
            for (int mt = 0; mt < 4; ++mt)
#pragma unroll
                for (int nt = 0; nt < 8; ++nt)
                    mma_f16(acc[mt][nt], aR[mt], bR[nt]);
        }
        __syncthreads();
    }

    /* ---- fused epilogue: thread holds contiguous d pair (2lc, 2lc+1) ---- */
#pragma unroll
    for (int mt = 0; mt < 4; ++mt) {
#pragma unroll
        for (int nt = 0; nt < 4; ++nt) {
            int d = d0 + warp_n * 32 + nt * 8 + 2 * lc;
            float2 bin = *reinterpret_cast<const float2*>(bias + d);
            float2 bfg = *reinterpret_cast<const float2*>(bias + D_ + d);

            int row = row0 + warp_m * 64 + mt * 16 + lr;
            {
                size_t off = (size_t)row * D_ + d;
                float2 xv = *reinterpret_cast<const float2*>(X + off);
                float2 av = *reinterpret_cast<const float2*>(AV + off);
                float2 o;
                o.x = sigmoidf_(acc[mt][nt][0] + bin.x) * xv.x +
                      sigmoidf_(acc[mt][nt + 4][0] + bfg.x) * av.x;
                o.y = sigmoidf_(acc[mt][nt][1] + bin.y) * xv.y +
                      sigmoidf_(acc[mt][nt + 4][1] + bfg.y) * av.y;
                *reinterpret_cast<float2*>(out + off) = o;
            }
            {
                size_t off = (size_t)(row + 8) * D_ + d;
                float2 xv = *reinterpret_cast<const float2*>(X + off);
                float2 av = *reinterpret_cast<const float2*>(AV + off);
                float2 o;
                o.x = sigmoidf_(acc[mt][nt][2] + bin.x) * xv.x +
                      sigmoidf_(acc[mt][nt + 4][2] + bfg.x) * av.x;
                o.y = sigmoidf_(acc[mt][nt][3] + bin.y) * xv.y +
                      sigmoidf_(acc[mt][nt + 4][3] + bfg.y) * av.y;
                *reinterpret_cast<float2*>(out + off) = o;
            }
        }
    }
}

/* ======================= host ======================= */
extern "C" void kernel_launch(void* const* d_in, const int* in_sizes, int n_in,
                              void* d_out, int out_size) {
    (void)in_sizes; (void)n_in; (void)out_size;
    const float* X    = (const float*)d_in[0];
    const float* W    = (const float*)d_in[1];
    const float* bias = (const float*)d_in[2];

    float* gating = (float*)d_out;
    float* avg    = (float*)d_out + (size_t)NTOT * D_;

    static bool attr_set = false;
    if (!attr_set) {
        cudaFuncSetAttribute(gate_gemm_f16,
                             cudaFuncAttributeMaxDynamicSharedMemorySize, SMEM_BYTES);
        attr_set = true;
    }

    __half* dW; cudaGetSymbolAddress((void**)&dW, h_W);

    cvt_f16<<<(K_ * K_ / 4 + 255) / 256, 256>>>(W, dW, K_ * K_ / 4);
    cumavg_part_cvt<<<B_ * NCH, 256>>>(X);
    chunk_prefix<<<8, 256>>>();
    cumavg_scan_v3<<<B_ * NCH, 256>>>(X, avg);

    dim3 grid(D_ / 64, NTOT / BM);   /* (16, 64) */
    gate_gemm_f16<<<grid, 256, SMEM_BYTES>>>(X, avg, bias, gating);
}

// round 8
// speedup vs baseline: 7.4664x; 1.1915x over previous
#include <cuda_runtime.h>
#include <cuda_fp16.h>
#include <cstdint>

#define B_ 8
#define L_ 2048
#define D_ 1024
#define NTOT (B_ * L_)       /* 16384 rows */
#define K_ (2 * D_)          /* 2048 reduction dim */

#define BM 128               /* rows per CTA */
#define BN 128               /* cols: [0,64)=in-gate dims, [64,128)=fg-gate dims */
#define BK 32                /* fp16 k per stage */
#define PITCH 40             /* halves per row */
#define STAGES 4
#define KTILES (K_ / BK)     /* 64 */

#define A_HALVES (STAGES * BM * PITCH)           /* 20480 */
#define SMEM_HALVES (A_HALVES + STAGES * BN * PITCH)
#define SMEM_BYTES (SMEM_HALVES * 2)             /* 81920 -> 2 CTAs/SM */

/* fp16 scratch (device globals -- no allocation) */
__device__ __half h_X[NTOT * D_];     /* 32 MB */
__device__ __half h_AV[NTOT * D_];    /* 32 MB */
__device__ __half h_W[K_ * K_];       /* 8 MB  */

__device__ __forceinline__ float sigmoidf_(float x) {
    return 1.0f / (1.0f + __expf(-x));
}

__device__ __forceinline__ void mma_f16(float* c, const uint32_t* a, const uint32_t* b) {
    asm volatile(
        "mma.sync.aligned.m16n8k16.row.col.f32.f16.f16.f32 "
        "{%0,%1,%2,%3}, {%4,%5,%6,%7}, {%8,%9}, {%0,%1,%2,%3};"
        : "+f"(c[0]), "+f"(c[1]), "+f"(c[2]), "+f"(c[3])
        : "r"(a[0]), "r"(a[1]), "r"(a[2]), "r"(a[3]), "r"(b[0]), "r"(b[1]));
}

__device__ __forceinline__ void ldsm_x4(uint32_t& r0, uint32_t& r1, uint32_t& r2,
                                        uint32_t& r3, uint32_t addr) {
    asm volatile("ldmatrix.sync.aligned.m8n8.x4.shared.b16 {%0,%1,%2,%3}, [%4];"
                 : "=r"(r0), "=r"(r1), "=r"(r2), "=r"(r3) : "r"(addr));
}

__device__ __forceinline__ void cp_async16(__half* s, const __half* g) {
    uint32_t sa = (uint32_t)__cvta_generic_to_shared(s);
    asm volatile("cp.async.cg.shared.global [%0], [%1], 16;" :: "r"(sa), "l"(g));
}
__device__ __forceinline__ void cp_commit() {
    asm volatile("cp.async.commit_group;");
}
template <int N>
__device__ __forceinline__ void cp_wait() {
    asm volatile("cp.async.wait_group %0;" :: "n"(N));
}

__device__ __forceinline__ uint2 pack_h4(float a, float b, float c, float d) {
    __half2 lo = __floats2half2_rn(a, b);
    __half2 hi = __floats2half2_rn(c, d);
    uint2 u;
    u.x = *reinterpret_cast<uint32_t*>(&lo);
    u.y = *reinterpret_cast<uint32_t*>(&hi);
    return u;
}

/* ======================= cumulative average (3-pass, float4) =========== */
#define CHUNK 16
#define NCH (L_ / CHUNK)   /* 128 */
#define D4 (D_ / 4)        /* 256 */
#define PART_BLOCKS (B_ * NCH)   /* 1024 */
#define CVT_BLOCKS 256
__device__ float g_part[B_ * NCH * D_];   /* 4 MB */

/* Pass 1: chunk sums + fused X->fp16 conversion; extra blocks convert W. */
__global__ void cumavg_part_cvt(const float* __restrict__ x,
                                const float* __restrict__ w) {
    int bid = blockIdx.x;
    if (bid >= PART_BLOCKS) {
        /* ---- W f32 -> f16 (256 blocks) ---- */
        int i0 = (bid - PART_BLOCKS) * 256 + threadIdx.x;
        const float4* src = reinterpret_cast<const float4*>(w);
        uint2* dst = reinterpret_cast<uint2*>(h_W);
#pragma unroll
        for (int j = 0; j < (K_ * K_ / 4) / (CVT_BLOCKS * 256); ++j) {
            int i = i0 + j * CVT_BLOCKS * 256;
            float4 v = src[i];
            dst[i] = pack_h4(v.x, v.y, v.z, v.w);
        }
        return;
    }
    int b = bid >> 7, c = bid & 127;
    int d4 = threadIdx.x;
    size_t base = ((size_t)b * L_ + c * CHUNK) * D4 + d4;
    const float4* px = reinterpret_cast<const float4*>(x) + base;
    uint2* ph = reinterpret_cast<uint2*>(h_X) + base;
    float4 s = {0.f, 0.f, 0.f, 0.f};
#pragma unroll
    for (int t = 0; t < CHUNK; ++t) {
        float4 v = px[(size_t)t * D4];
        s.x += v.x; s.y += v.y; s.z += v.z; s.w += v.w;
        ph[(size_t)t * D4] = pack_h4(v.x, v.y, v.z, v.w);
    }
    reinterpret_cast<float4*>(g_part)[(b * NCH + c) * D4 + d4] = s;
}

/* Pass 2: exclusive prefix over the NCH chunk sums. 8 blocks x 256 thr. */
__global__ void chunk_prefix() {
    int b = blockIdx.x, d4 = threadIdx.x;
    float4* gp = reinterpret_cast<float4*>(g_part);
    float4 run = {0.f, 0.f, 0.f, 0.f};
#pragma unroll 8
    for (int c = 0; c < NCH; ++c) {
        size_t i = (size_t)(b * NCH + c) * D4 + d4;
        float4 v = gp[i];
        gp[i] = run;
        run.x += v.x; run.y += v.y; run.z += v.z; run.w += v.w;
    }
}

/* Pass 3: scan + divide, writes avg f32 + h_AV fp16. 1024 blocks. */
__global__ void cumavg_scan_v3(const float* __restrict__ x, float* __restrict__ avg) {
    int b = blockIdx.x >> 7, c = blockIdx.x & 127;
    int d4 = threadIdx.x;
    int t0 = c * CHUNK;
    float4 run = reinterpret_cast<const float4*>(g_part)[(b * NCH + c) * D4 + d4];
    size_t base = ((size_t)b * L_ + t0) * D4 + d4;
    const float4* px = reinterpret_cast<const float4*>(x) + base;
    float4* pa = reinterpret_cast<float4*>(avg) + base;
    uint2* ph = reinterpret_cast<uint2*>(h_AV) + base;
#pragma unroll
    for (int t = 0; t < CHUNK; ++t) {
        float4 v = px[(size_t)t * D4];
        run.x += v.x; run.y += v.y; run.z += v.z; run.w += v.w;
        float r = 1.0f / (float)(t0 + t + 1);
        float4 a = {run.x * r, run.y * r, run.z * r, run.w * r};
        pa[(size_t)t * D4] = a;
        ph[(size_t)t * D4] = pack_h4(a.x, a.y, a.z, a.w);
    }
}

/* ======================= fp16 tensor GEMM + fused gating ================ */
/* 4 warps, warp grid 2(m) x 2(n), warp tile 64x64 (32 in + 32 fg dims).
   2 CTAs/SM so sync bubbles of one CTA are filled by the other. */
__global__ __launch_bounds__(128, 2)
void gate_gemm_f16(const float* __restrict__ X,
                   const float* __restrict__ AV,
                   const float* __restrict__ bias,
                   float* __restrict__ out)
{
    extern __shared__ __half smem[];
    __half* Asm = smem;                  /* [STAGES][BM][PITCH] */
    __half* Bsm = smem + A_HALVES;       /* [STAGES][BN][PITCH] */

    const int tid    = threadIdx.x;
    const int lane   = tid & 31;
    const int wid    = tid >> 5;         /* 0..3 */
    const int warp_m = wid & 1;          /* 2 warps along M (64 rows each) */
    const int warp_n = wid >> 1;         /* 2 warps along N (32 dims each) */
    const int lr     = lane >> 2;
    const int lc     = lane & 3;

    const int bn   = blockIdx.x;         /* 0..15 -> dims [bn*64, bn*64+64) */
    const int bm   = blockIdx.y;         /* 0..127 */
    const int row0 = bm * BM;
    const int d0   = bn * 64;

    const uint32_t As_u32 = (uint32_t)__cvta_generic_to_shared(Asm);
    const uint32_t Bs_u32 = (uint32_t)__cvta_generic_to_shared(Bsm);

    const int a_lane = (lane & 15) * PITCH + (lane >> 4) * 8;
    const int b_lane = ((lane & 7) + ((lane >> 4) << 3)) * PITCH + (((lane >> 3) & 1) << 3);

    float acc[4][8][4];
#pragma unroll
    for (int i = 0; i < 4; i++)
#pragma unroll
        for (int j = 0; j < 8; j++)
#pragma unroll
            for (int r = 0; r < 4; r++) acc[i][j][r] = 0.0f;

    /* 128 threads: A = 512 chunks (4/thread), B = 512 chunks (4/thread) */
    auto load_tiles = [&](int kt, int stg) {
        const int kb = kt * BK;
        const __half* asrc = (kb < D_) ? h_X : h_AV;
        const int akb = (kb < D_) ? kb : (kb - D_);
        __half* As = Asm + stg * (BM * PITCH);
        __half* Bs = Bsm + stg * (BN * PITCH);
#pragma unroll
        for (int j = 0; j < 4; ++j) {
            int idx = tid + 128 * j;
            int row = idx >> 2;
            int off = (idx & 3) * 8;
            cp_async16(As + row * PITCH + off,
                       asrc + (size_t)(row0 + row) * D_ + akb + off);
        }
#pragma unroll
        for (int j = 0; j < 4; ++j) {
            int idx = tid + 128 * j;
            int n   = idx >> 2;
            int off = (idx & 3) * 8;
            int o = (n < 64) ? (d0 + n) : (D_ + d0 + (n - 64));
            cp_async16(Bs + n * PITCH + off,
                       h_W + (size_t)o * K_ + kb + off);
        }
        cp_commit();
    };

    load_tiles(0, 0);
    load_tiles(1, 1);
    load_tiles(2, 2);

    for (int kt = 0; kt < KTILES; ++kt) {
        if (kt + 3 < KTILES) {
            load_tiles(kt + 3, (kt + 3) % STAGES);
            cp_wait<3>();
        } else if (kt + 2 < KTILES) {
            cp_wait<2>();
        } else if (kt + 1 < KTILES) {
            cp_wait<1>();
        } else {
            cp_wait<0>();
        }
        __syncthreads();

        const int st = kt % STAGES;
        const uint32_t a_base = As_u32 + 2 * (st * (BM * PITCH) + warp_m * 64 * PITCH + a_lane);
        const uint32_t b_base = Bs_u32 + 2 * (st * (BN * PITCH) + b_lane);

#pragma unroll
        for (int ks = 0; ks < 2; ++ks) {
            uint32_t aR[4][4];
            uint32_t bR[8][2];
#pragma unroll
            for (int mt = 0; mt < 4; ++mt)
                ldsm_x4(aR[mt][0], aR[mt][1], aR[mt][2], aR[mt][3],
                        a_base + 2 * (mt * 16 * PITCH + ks * 16));
#pragma unroll
            for (int ntp = 0; ntp < 4; ++ntp) {
                int nt = 2 * ntp;
                int fnt = (nt < 4) ? (warp_n * 32 + nt * 8)
                                   : (64 + warp_n * 32 + (nt - 4) * 8);
                ldsm_x4(bR[nt][0], bR[nt][1], bR[nt + 1][0], bR[nt + 1][1],
                        b_base + 2 * (fnt * PITCH + ks * 16));
            }
#pragma unroll
            for (int mt = 0; mt < 4; ++mt)
#pragma unroll
                for (int nt = 0; nt < 8; ++nt)
                    mma_f16(acc[mt][nt], aR[mt], bR[nt]);
        }
        __syncthreads();
    }

    /* ---- fused epilogue: thread holds contiguous d pair (2lc, 2lc+1) ---- */
#pragma unroll
    for (int mt = 0; mt < 4; ++mt) {
#pragma unroll
        for (int nt = 0; nt < 4; ++nt) {
            int d = d0 + warp_n * 32 + nt * 8 + 2 * lc;
            float2 bin = *reinterpret_cast<const float2*>(bias + d);
            float2 bfg = *reinterpret_cast<const float2*>(bias + D_ + d);

            int row = row0 + warp_m * 64 + mt * 16 + lr;
            {
                size_t off = (size_t)row * D_ + d;
                float2 xv = *reinterpret_cast<const float2*>(X + off);
                float2 av = *reinterpret_cast<const float2*>(AV + off);
                float2 o;
                o.x = sigmoidf_(acc[mt][nt][0] + bin.x) * xv.x +
                      sigmoidf_(acc[mt][nt + 4][0] + bfg.x) * av.x;
                o.y = sigmoidf_(acc[mt][nt][1] + bin.y) * xv.y +
                      sigmoidf_(acc[mt][nt + 4][1] + bfg.y) * av.y;
                *reinterpret_cast<float2*>(out + off) = o;
            }
            {
                size_t off = (size_t)(row + 8) * D_ + d;
                float2 xv = *reinterpret_cast<const float2*>(X + off);
                float2 av = *reinterpret_cast<const float2*>(AV + off);
                float2 o;
                o.x = sigmoidf_(acc[mt][nt][2] + bin.x) * xv.x +
                      sigmoidf_(acc[mt][nt + 4][2] + bfg.x) * av.x;
                o.y = sigmoidf_(acc[mt][nt][3] + bin.y) * xv.y +
                      sigmoidf_(acc[mt][nt + 4][3] + bfg.y) * av.y;
                *reinterpret_cast<float2*>(out + off) = o;
            }
        }
    }
}

/* ======================= host ======================= */
extern "C" void kernel_launch(void* const* d_in, const int* in_sizes, int n_in,
                              void* d_out, int out_size) {
    (void)in_sizes; (void)n_in; (void)out_size;
    const float* X    = (const float*)d_in[0];
    const float* W    = (const float*)d_in[1];
    const float* bias = (const float*)d_in[2];

    float* gating = (float*)d_out;
    float* avg    = (float*)d_out + (size_t)NTOT * D_;

    static bool attr_set = false;
    if (!attr_set) {
        cudaFuncSetAttribute(gate_gemm_f16,
                             cudaFuncAttributeMaxDynamicSharedMemorySize, SMEM_BYTES);
        attr_set = true;
    }

    cumavg_part_cvt<<<PART_BLOCKS + CVT_BLOCKS, 256>>>(X, W);
    chunk_prefix<<<B_, 256>>>();
    cumavg_scan_v3<<<PART_BLOCKS, 256>>>(X, avg);

    dim3 grid(D_ / 64, NTOT / BM);   /* (16, 128) */
    gate_gemm_f16<<<grid, 128, SMEM_BYTES>>>(X, avg, bias, gating);
}